// round 7
// baseline (speedup 1.0000x reference)
#include <cuda_runtime.h>
#include <cuda_bf16.h>
#include <cstdint>

// ---------------------------------------------------------------------------
// SCNLinkPredictor — mma.sync tf32, BE=128, 2x4 warp tiling, row-major A.
//
//  k0 clear flags | k1 CN counts (+distinct-value compaction)
//  k2 CN-MLP table (compacted list, 64 blocks) | k3 weight permute+tf32
//  k4 main: per-CTA 128 edges: P=xi*xj -> SMEM A (row-major, stride 260)
//     3x [ mma.sync m16n8k8 tf32 (M128,N256,K256), W streamed 32-K chunks,
//          2-deep cp.async ring, fragment-permuted W in gmem ->
//          epilogue(bias/relu/beta*table) -> SMEM A ]
//     final layer folded into fragments.
// ---------------------------------------------------------------------------

#define MAXE   131072
#define HD     256
#define NCOUNT 4097
#define BE     128
#define ASTR   260              // A row stride in floats (bank-conflict-free)

__device__ int g_counts[MAXE];
__device__ int g_flags[NCOUNT];
__device__ int g_vals[NCOUNT];
__device__ int g_nvals;
__device__ __align__(16) float    g_table[NCOUNT * HD];
__device__ __align__(16) uint32_t g_wtf[3 * HD * HD];  // fragment-permuted tf32 W

// ---------------- SMEM layout (dynamic) ----------------
#define ACT_OFF   0                        // 128 x 260 f32 = 133120 B
#define WB_OFF    133120                   // 2 ring buffers x 32768 B
#define WB_STRIDE 32768
#define BIAS_OFF  (WB_OFF + 2 * WB_STRIDE) // 198656: [b1|b2|lb1|lw2]
#define SMEM_SZ   (BIAS_OFF + 4096)        // 202752

// ---------------- PTX helpers ----------------
__device__ __forceinline__ uint32_t smem_u32(const void* p) {
    uint32_t a;
    asm("{ .reg .u64 t; cvta.to.shared.u64 t, %1; cvt.u32.u64 %0, t; }"
        : "=r"(a) : "l"(p));
    return a;
}
__device__ __forceinline__ uint32_t f2tf(float f) {
    uint32_t r;
    asm("cvt.rna.tf32.f32 %0, %1;" : "=r"(r) : "f"(f));
    return r;
}
__device__ __forceinline__ void mma8(float* c, const uint32_t* a,
                                     uint32_t b0, uint32_t b1) {
    asm volatile(
        "mma.sync.aligned.m16n8k8.row.col.f32.tf32.tf32.f32 "
        "{%0,%1,%2,%3}, {%4,%5,%6,%7}, {%8,%9}, {%0,%1,%2,%3};"
        : "+f"(c[0]), "+f"(c[1]), "+f"(c[2]), "+f"(c[3])
        : "r"(a[0]), "r"(a[1]), "r"(a[2]), "r"(a[3]), "r"(b0), "r"(b1));
}
__device__ __forceinline__ void lds128(uint32_t* v, uint32_t addr) {
    asm volatile("ld.shared.v4.b32 {%0,%1,%2,%3}, [%4];"
                 : "=r"(v[0]), "=r"(v[1]), "=r"(v[2]), "=r"(v[3]) : "r"(addr));
}
__device__ __forceinline__ uint32_t lds32(uint32_t addr) {
    uint32_t v;
    asm volatile("ld.shared.b32 %0, [%1];" : "=r"(v) : "r"(addr));
    return v;
}
__device__ __forceinline__ void sts32(uint32_t addr, uint32_t v) {
    asm volatile("st.shared.b32 [%0], %1;" :: "r"(addr), "r"(v));
}
__device__ __forceinline__ void sts64(uint32_t addr, uint32_t v0, uint32_t v1) {
    asm volatile("st.shared.v2.b32 [%0], {%1,%2};" :: "r"(addr), "r"(v0), "r"(v1));
}
__device__ __forceinline__ void sts128(uint32_t addr, uint32_t v0, uint32_t v1,
                                       uint32_t v2, uint32_t v3) {
    asm volatile("st.shared.v4.b32 [%0], {%1,%2,%3,%4};"
                 :: "r"(addr), "r"(v0), "r"(v1), "r"(v2), "r"(v3));
}
#define CP_ASYNC16(dst, src) \
    asm volatile("cp.async.cg.shared.global [%0], [%1], 16;" :: "r"(dst), "l"(src))
#define CP_COMMIT() asm volatile("cp.async.commit_group;" ::: "memory")
#define CP_WAIT0()  asm volatile("cp.async.wait_group 0;" ::: "memory")

// ---------------- k0: clear ----------------
__global__ void clear_flags_kernel() {
    int i = blockIdx.x * blockDim.x + threadIdx.x;
    if (i < NCOUNT) g_flags[i] = 0;
    if (i == 0) g_nvals = 0;
}

// ---------------- k1: CN counts + compaction ----------------
__global__ void cn_count_kernel(const int* __restrict__ nbr,
                                const int* __restrict__ tar, int E) {
    int w = (blockIdx.x * blockDim.x + threadIdx.x) >> 5;
    int lane = threadIdx.x & 31;
    if (w >= E) return;
    int s = tar[w];
    int d = tar[E + w];
    int2 a = ((const int2*)(nbr + (size_t)s * 64))[lane];
    int2 b = ((const int2*)(nbr + (size_t)d * 64))[lane];
    int cnt = 0;
#pragma unroll
    for (int j = 0; j < 32; j++) {
        int v0 = __shfl_sync(0xffffffffu, b.x, j);
        int v1 = __shfl_sync(0xffffffffu, b.y, j);
        cnt += (a.x == v0) + (a.y == v0) + (a.x == v1) + (a.y == v1);
    }
#pragma unroll
    for (int off = 16; off; off >>= 1)
        cnt += __shfl_xor_sync(0xffffffffu, cnt, off);
    if (lane == 0) {
        g_counts[w] = cnt;
        if (atomicExch(&g_flags[cnt], 1) == 0) {
            int idx = atomicAdd(&g_nvals, 1);
            g_vals[idx] = cnt;
        }
    }
}

// ---------------- k2: CN MLP table (compacted) ----------------
__global__ void cn_table_kernel(const float* __restrict__ w1, const float* __restrict__ b1,
                                const float* __restrict__ w2, const float* __restrict__ b2,
                                const float* __restrict__ w3, const float* __restrict__ b3) {
    __shared__ float sh[HD];
    int h = threadIdx.x;
    int nv = g_nvals;
    for (int i = blockIdx.x; i < nv; i += gridDim.x) {
        int c = g_vals[i];
        float cf = (float)c;
        sh[h] = fmaxf(fmaf(cf, w1[h], b1[h]), 0.f);
        __syncthreads();
        float s = b2[h];
#pragma unroll 8
        for (int k = 0; k < HD; k++) s = fmaf(sh[k], w2[k * HD + h], s);
        s = fmaxf(s, 0.f);
        __syncthreads();
        sh[h] = s;
        __syncthreads();
        float t = b3[h];
#pragma unroll 8
        for (int k = 0; k < HD; k++) t = fmaf(sh[k], w3[k * HD + h], t);
        g_table[c * HD + h] = t;
        __syncthreads();
    }
}

// ---------------- k3: permute + tf32-round weights ----------------
// Output order: [mat(3)][chunk c(8)][kstep ks(4)][ntpair(16)][lane(32)][j(4)]
//   j: {b0(nt=2p), b1(2p), b0(2p+1), b1(2p+1)}
//   b0: k = c*32 + ks*8 + (lane&3),     n = nt*8 + (lane>>2)
//   b1: k = c*32 + ks*8 + (lane&3) + 4, same n
__global__ void wprep_kernel(const float* __restrict__ w0,
                             const float* __restrict__ w1,
                             const float* __restrict__ w2) {
    int i = blockIdx.x * blockDim.x + threadIdx.x;
    if (i >= 3 * HD * HD) return;
    int j    = i & 3;
    int lane = (i >> 2) & 31;
    int ntp  = (i >> 7) & 15;
    int ks   = (i >> 11) & 3;
    int c    = (i >> 13) & 7;
    int mat  = i >> 16;
    int nt = ntp * 2 + (j >> 1);
    int k  = c * 32 + ks * 8 + (lane & 3) + (j & 1) * 4;
    int n  = nt * 8 + (lane >> 2);
    const float* w = (mat == 0) ? w0 : (mat == 1) ? w1 : w2;
    g_wtf[i] = f2tf(w[k * HD + n]);
}

// ---------------- main kernel ----------------
__device__ __forceinline__ void load_wchunk(uint32_t sb, int buf, int t) {
    int tx = threadIdx.x;
    const uint32_t* src = g_wtf + (size_t)t * 8192;
    uint32_t dst = sb + WB_OFF + buf * WB_STRIDE;
#pragma unroll
    for (int it = 0; it < 8; ++it) {
        int u = it * 256 + tx;
        CP_ASYNC16(dst + u * 16, src + u * 4);
    }
    CP_COMMIT();
}

// epilogue: act = f(C + bias [+ beta*table]) -> row-major SMEM A (tf32)
template <int RELU, int TAB>
__device__ __forceinline__ void epilogue(uint32_t sb, float acc[4][8][4],
                                         const float* __restrict__ bias,
                                         const int* __restrict__ s_tbl,
                                         float beta, int wm, int wn, int lane) {
    int q = lane & 3, gid = lane >> 2;
#pragma unroll
    for (int mt = 0; mt < 4; ++mt) {
        int r0 = wm * 64 + mt * 16 + gid;
        int trow0 = 0, trow1 = 0;
        if (TAB) { trow0 = s_tbl[r0]; trow1 = s_tbl[r0 + 8]; }
#pragma unroll
        for (int nt = 0; nt < 8; ++nt) {
            int colb = wn * 64 + nt * 8 + 2 * q;
            float2 bv = *(const float2*)(bias + colb);
            float v0 = acc[mt][nt][0] + bv.x;
            float v1 = acc[mt][nt][1] + bv.y;
            float v2 = acc[mt][nt][2] + bv.x;
            float v3 = acc[mt][nt][3] + bv.y;
            if (TAB) {
                float2 t0 = __ldg((const float2*)(g_table + trow0 + colb));
                float2 t1 = __ldg((const float2*)(g_table + trow1 + colb));
                v0 = fmaf(beta, t0.x, v0); v1 = fmaf(beta, t0.y, v1);
                v2 = fmaf(beta, t1.x, v2); v3 = fmaf(beta, t1.y, v3);
            }
            if (RELU) {
                v0 = fmaxf(v0, 0.f); v1 = fmaxf(v1, 0.f);
                v2 = fmaxf(v2, 0.f); v3 = fmaxf(v3, 0.f);
            }
            uint32_t a0 = sb + ACT_OFF + (uint32_t)(r0 * ASTR + colb) * 4;
            sts64(a0, f2tf(v0), f2tf(v1));                  // row r0
            sts64(a0 + 8 * ASTR * 4, f2tf(v2), f2tf(v3));   // row r0+8
        }
    }
}

__global__ void __launch_bounds__(256, 1)
scn_mma_kernel(const float* __restrict__ x, const int* __restrict__ tar,
               const float* __restrict__ beta_p,
               const float* __restrict__ ijb1, const float* __restrict__ ijb2,
               const float* __restrict__ lb1,  const float* __restrict__ lw2,
               const float* __restrict__ lb2,  float* __restrict__ out, int E) {
    extern __shared__ char smem[];
    uint32_t sb = smem_u32(smem);
    int tx = threadIdx.x, w = tx >> 5, lane = tx & 31;
    int q = lane & 3, gid = lane >> 2;
    int wm = w & 1, wn = w >> 1;           // 2 M-groups x 4 N-groups
    int e0 = blockIdx.x * BE;

    __shared__ int   s_src[BE], s_dst[BE], s_tbl[BE];
    __shared__ float s_red[BE];

    load_wchunk(sb, 0, 0);                  // prefetch chunk 0 under gather

    float* sbias = (float*)(smem + BIAS_OFF);
    for (int i = tx; i < 1024; i += 256) {
        float v;
        if      (i < 256) v = ijb1[i];
        else if (i < 512) v = ijb2[i - 256];
        else if (i < 768) v = lb1[i - 512];
        else              v = lw2[i - 768];
        sbias[i] = v;
    }
    if (tx < BE) {
        int e = e0 + tx; if (e >= E) e = E - 1;
        s_src[tx] = tar[e];
        s_dst[tx] = tar[E + e];
        s_tbl[tx] = g_counts[e] * HD;
        s_red[tx] = 0.f;
    }
    __syncthreads();

    float beta = *beta_p;
    float lb2v = *lb2;

    // ---- gather: A = tf32(xi * xj), row-major stride ASTR ----
#pragma unroll 4
    for (int it = 0; it < 32; ++it) {
        int i = it * 256 + tx;              // 8192 float4 slots
        int m = i >> 6, c4 = i & 63;
        const float4* xa = (const float4*)(x + (size_t)s_src[m] * HD);
        const float4* xb = (const float4*)(x + (size_t)s_dst[m] * HD);
        float4 a = xa[c4], b = xb[c4];
        sts128(sb + ACT_OFF + (uint32_t)(m * ASTR) * 4 + c4 * 16,
               f2tf(a.x * b.x), f2tf(a.y * b.y),
               f2tf(a.z * b.z), f2tf(a.w * b.w));
    }

    float acc[4][8][4];

#pragma unroll 1
    for (int t = 0; t < 24; ++t) {
        int c = t & 7, g = t >> 3;
        CP_WAIT0();                         // chunk t landed (this thread)
        __syncthreads();                    // visible to all; prev MMAs done
        if (t + 1 < 24) load_wchunk(sb, (t + 1) & 1, t + 1);
        if (c == 0) {
#pragma unroll
            for (int mt = 0; mt < 4; ++mt)
#pragma unroll
                for (int nt = 0; nt < 8; ++nt)
#pragma unroll
                    for (int i = 0; i < 4; ++i) acc[mt][nt][i] = 0.f;
        }

        uint32_t bbase = sb + WB_OFF + (t & 1) * WB_STRIDE
                       + (uint32_t)(wn * 4) * 512 + lane * 16;
        uint32_t abase = sb + ACT_OFF
                       + (uint32_t)((wm * 64 + gid) * ASTR + q) * 4;
#pragma unroll
        for (int ks = 0; ks < 4; ++ks) {
            int kstep = c * 4 + ks;
            uint32_t a[4][4];
#pragma unroll
            for (int mt = 0; mt < 4; ++mt) {
                uint32_t ab = abase + (uint32_t)(mt * 16 * ASTR) * 4 + kstep * 32;
                a[mt][0] = lds32(ab);
                a[mt][1] = lds32(ab + 8 * ASTR * 4);
                a[mt][2] = lds32(ab + 16);
                a[mt][3] = lds32(ab + 8 * ASTR * 4 + 16);
            }
            uint32_t bv[4][4];
#pragma unroll
            for (int p = 0; p < 4; ++p)
                lds128(bv[p], bbase + (uint32_t)(ks * 16 + p) * 512);
#pragma unroll
            for (int mt = 0; mt < 4; ++mt)
#pragma unroll
                for (int p = 0; p < 4; ++p) {
                    mma8(acc[mt][2 * p],     a[mt], bv[p][0], bv[p][1]);
                    mma8(acc[mt][2 * p + 1], a[mt], bv[p][2], bv[p][3]);
                }
        }

        if (c == 7) {
            __syncthreads();                // all MMAs done reading ACT
            if (g == 0) {
                epilogue<1, 0>(sb, acc, sbias,       s_tbl, beta, wm, wn, lane);
            } else if (g == 1) {
                epilogue<0, 1>(sb, acc, sbias + 256, s_tbl, beta, wm, wn, lane);
            } else {
                // final: out = relu(C + lb1) . lw2 + lb2, folded in fragments
#pragma unroll
                for (int mt = 0; mt < 4; ++mt) {
                    float p0 = 0.f, p1 = 0.f;
#pragma unroll
                    for (int nt = 0; nt < 8; ++nt) {
                        int colb = wn * 64 + nt * 8 + 2 * q;
                        float2 lb = *(const float2*)(sbias + 512 + colb);
                        float2 lw = *(const float2*)(sbias + 768 + colb);
                        p0 = fmaf(fmaxf(acc[mt][nt][0] + lb.x, 0.f), lw.x, p0);
                        p0 = fmaf(fmaxf(acc[mt][nt][1] + lb.y, 0.f), lw.y, p0);
                        p1 = fmaf(fmaxf(acc[mt][nt][2] + lb.x, 0.f), lw.x, p1);
                        p1 = fmaf(fmaxf(acc[mt][nt][3] + lb.y, 0.f), lw.y, p1);
                    }
                    p0 += __shfl_xor_sync(0xffffffffu, p0, 1);
                    p0 += __shfl_xor_sync(0xffffffffu, p0, 2);
                    p1 += __shfl_xor_sync(0xffffffffu, p1, 1);
                    p1 += __shfl_xor_sync(0xffffffffu, p1, 2);
                    if (q == 0) {
                        int r0 = wm * 64 + mt * 16 + gid;
                        atomicAdd(&s_red[r0],     p0);
                        atomicAdd(&s_red[r0 + 8], p1);
                    }
                }
            }
        }
    }

    __syncthreads();
    if (tx < BE && e0 + tx < E) out[e0 + tx] = s_red[tx] + lb2v;
}

// ---------------------------------------------------------------------------
extern "C" void kernel_launch(void* const* d_in, const int* in_sizes, int n_in,
                              void* d_out, int out_size) {
    const float* x    = (const float*)d_in[0];
    const int*   nbr  = (const int*)d_in[1];
    const int*   tar  = (const int*)d_in[2];
    const float* beta = (const float*)d_in[3];
    const float* cw1  = (const float*)d_in[4];
    const float* cb1  = (const float*)d_in[5];
    const float* cw2  = (const float*)d_in[6];
    const float* cb2  = (const float*)d_in[7];
    const float* cw3  = (const float*)d_in[8];
    const float* cb3  = (const float*)d_in[9];
    const float* ijw1 = (const float*)d_in[10];
    const float* ijb1 = (const float*)d_in[11];
    const float* ijw2 = (const float*)d_in[12];
    const float* ijb2 = (const float*)d_in[13];
    const float* lw1  = (const float*)d_in[14];
    const float* lb1  = (const float*)d_in[15];
    const float* lw2  = (const float*)d_in[16];
    const float* lb2  = (const float*)d_in[17];
    float* out = (float*)d_out;

    int E = in_sizes[2] / 2;
    if (E > MAXE) E = MAXE;

    cudaFuncSetAttribute(scn_mma_kernel,
                         cudaFuncAttributeMaxDynamicSharedMemorySize, SMEM_SZ);

    clear_flags_kernel<<<(NCOUNT + 255) / 256, 256>>>();
    wprep_kernel<<<(3 * HD * HD + 255) / 256, 256>>>(ijw1, ijw2, lw1);
    cn_count_kernel<<<(E + 7) / 8, 256>>>(nbr, tar, E);
    cn_table_kernel<<<64, 256>>>(cw1, cb1, cw2, cb2, cw3, cb3);
    scn_mma_kernel<<<(E + BE - 1) / BE, 256, SMEM_SZ>>>(
        x, tar, beta, ijb1, ijb2, lb1, lw2, lb2, out, E);
}

// round 8
// speedup vs baseline: 2.2963x; 2.2963x over previous
#include <cuda_runtime.h>
#include <cuda_fp16.h>
#include <cuda_bf16.h>
#include <cstdint>

// ---------------------------------------------------------------------------
// SCNLinkPredictor — fp16 mma.sync m16n8k16 pipeline.
//  k0 clear | k1 CN counts (+compaction) | k2a/k2b CN-MLP table (k-split)
//  k3 weight permute->fp16 | k4 main: BE=128 edges/CTA, 2x4 warp tiling,
//     A row-major fp16 (stride 264), W streamed in 64-K chunks (2-deep ring),
//     ldmatrix A fragments, 3 chained GEMMs + fused epilogues.
// ---------------------------------------------------------------------------

#define MAXE   131072
#define HD     256
#define NCOUNT 4097
#define BE     128
#define ASTRH  264              // A row stride in halves

__device__ int g_counts[MAXE];
__device__ int g_flags[NCOUNT];
__device__ int g_vals[NCOUNT];
__device__ int g_nvals;
__device__ __align__(16) float    g_table[NCOUNT * HD];
__device__ __align__(16) float    g_h2[NCOUNT * HD];
__device__ __align__(16) uint32_t g_whf[3 * HD * HD / 2];  // permuted fp16 W

// ---------------- SMEM layout (dynamic) ----------------
#define ACT_OFF   0                        // 128 x 264 halves = 67584 B
#define WB_OFF    67584                    // 2 ring buffers x 32768 B
#define WB_STRIDE 32768
#define BIAS_OFF  (WB_OFF + 2 * WB_STRIDE) // 133120: [b1|b2|lb1|lw2] f32
#define SMEM_SZ   (BIAS_OFF + 4096)        // 137216

// ---------------- PTX helpers ----------------
__device__ __forceinline__ uint32_t smem_u32(const void* p) {
    uint32_t a;
    asm("{ .reg .u64 t; cvta.to.shared.u64 t, %1; cvt.u32.u64 %0, t; }"
        : "=r"(a) : "l"(p));
    return a;
}
__device__ __forceinline__ void mma16(float* c, const uint32_t* a,
                                      uint32_t b0, uint32_t b1) {
    asm volatile(
        "mma.sync.aligned.m16n8k16.row.col.f32.f16.f16.f32 "
        "{%0,%1,%2,%3}, {%4,%5,%6,%7}, {%8,%9}, {%0,%1,%2,%3};"
        : "+f"(c[0]), "+f"(c[1]), "+f"(c[2]), "+f"(c[3])
        : "r"(a[0]), "r"(a[1]), "r"(a[2]), "r"(a[3]), "r"(b0), "r"(b1));
}
__device__ __forceinline__ void ldmx4(uint32_t* v, uint32_t addr) {
    asm volatile("ldmatrix.sync.aligned.m8n8.x4.shared.b16 {%0,%1,%2,%3}, [%4];"
                 : "=r"(v[0]), "=r"(v[1]), "=r"(v[2]), "=r"(v[3]) : "r"(addr));
}
__device__ __forceinline__ void lds128(uint32_t* v, uint32_t addr) {
    asm volatile("ld.shared.v4.b32 {%0,%1,%2,%3}, [%4];"
                 : "=r"(v[0]), "=r"(v[1]), "=r"(v[2]), "=r"(v[3]) : "r"(addr));
}
__device__ __forceinline__ void sts32(uint32_t addr, uint32_t v) {
    asm volatile("st.shared.b32 [%0], %1;" :: "r"(addr), "r"(v));
}
__device__ __forceinline__ void sts128(uint32_t addr, uint32_t v0, uint32_t v1,
                                       uint32_t v2, uint32_t v3) {
    asm volatile("st.shared.v4.b32 [%0], {%1,%2,%3,%4};"
                 :: "r"(addr), "r"(v0), "r"(v1), "r"(v2), "r"(v3));
}
__device__ __forceinline__ uint32_t h2u(float lo, float hi) {
    __half2 h = __floats2half2_rn(lo, hi);
    return *(uint32_t*)&h;
}
#define CP_ASYNC16(dst, src) \
    asm volatile("cp.async.cg.shared.global [%0], [%1], 16;" :: "r"(dst), "l"(src))
#define CP_COMMIT() asm volatile("cp.async.commit_group;" ::: "memory")
#define CP_WAIT0()  asm volatile("cp.async.wait_group 0;" ::: "memory")

// ---------------- k0: clear ----------------
__global__ void clear_flags_kernel() {
    int i = blockIdx.x * blockDim.x + threadIdx.x;
    if (i < NCOUNT) g_flags[i] = 0;
    if (i == 0) g_nvals = 0;
}

// ---------------- k1: CN counts + compaction ----------------
__global__ void cn_count_kernel(const int* __restrict__ nbr,
                                const int* __restrict__ tar, int E) {
    int w = (blockIdx.x * blockDim.x + threadIdx.x) >> 5;
    int lane = threadIdx.x & 31;
    if (w >= E) return;
    int s = tar[w];
    int d = tar[E + w];
    int2 a = ((const int2*)(nbr + (size_t)s * 64))[lane];
    int2 b = ((const int2*)(nbr + (size_t)d * 64))[lane];
    int cnt = 0;
#pragma unroll
    for (int j = 0; j < 32; j++) {
        int v0 = __shfl_sync(0xffffffffu, b.x, j);
        int v1 = __shfl_sync(0xffffffffu, b.y, j);
        cnt += (a.x == v0) + (a.y == v0) + (a.x == v1) + (a.y == v1);
    }
#pragma unroll
    for (int off = 16; off; off >>= 1)
        cnt += __shfl_xor_sync(0xffffffffu, cnt, off);
    if (lane == 0) {
        g_counts[w] = cnt;
        if (atomicExch(&g_flags[cnt], 1) == 0) {
            int idx = atomicAdd(&g_nvals, 1);
            g_vals[idx] = cnt;
        }
    }
}

// ---------------- k2a: table layer 2 (h2 = relu(relu(c*w1+b1)@w2 + b2)) ----
// grid 8 blocks: block b owns h in [b*32, b*32+32). 8 warps = 8 k-slices.
// w2 slice (32 k x 32 h per warp) loaded to registers ONCE, reused per value.
__global__ void table_l2_kernel(const float* __restrict__ w1, const float* __restrict__ b1,
                                const float* __restrict__ w2, const float* __restrict__ b2) {
    __shared__ float s_w1[HD], s_b1[HD];
    __shared__ float red[8][33];
    int tx = threadIdx.x, lane = tx & 31, wk = tx >> 5;
    int h = blockIdx.x * 32 + lane;
    for (int i = tx; i < HD; i += 256) { s_w1[i] = w1[i]; s_b1[i] = b1[i]; }
    float wr[32];
#pragma unroll 8
    for (int kk = 0; kk < 32; ++kk)
        wr[kk] = w2[(wk * 32 + kk) * HD + h];
    __syncthreads();
    int nv = g_nvals;
    float b2v = b2[h];
    for (int i = 0; i < nv; ++i) {
        float cf = (float)g_vals[i];
        float p = 0.f;
#pragma unroll 8
        for (int kk = 0; kk < 32; ++kk) {
            int k = wk * 32 + kk;
            p = fmaf(fmaxf(fmaf(cf, s_w1[k], s_b1[k]), 0.f), wr[kk], p);
        }
        red[wk][lane] = p;
        __syncthreads();
        if (wk == 0) {
            float s = b2v;
#pragma unroll
            for (int j = 0; j < 8; ++j) s += red[j][lane];
            g_h2[i * HD + h] = fmaxf(s, 0.f);
        }
        __syncthreads();
    }
}

// ---------------- k2b: table layer 3 (table[c] = h2 @ w3 + b3) ----------------
__global__ void table_l3_kernel(const float* __restrict__ w3, const float* __restrict__ b3) {
    __shared__ float red[8][33];
    __shared__ float s_h2[HD];
    int tx = threadIdx.x, lane = tx & 31, wk = tx >> 5;
    int h = blockIdx.x * 32 + lane;
    float wr[32];
#pragma unroll 8
    for (int kk = 0; kk < 32; ++kk)
        wr[kk] = w3[(wk * 32 + kk) * HD + h];
    int nv = g_nvals;
    float b3v = b3[h];
    for (int i = 0; i < nv; ++i) {
        for (int j = tx; j < HD; j += 256) s_h2[j] = g_h2[i * HD + j];
        __syncthreads();
        float p = 0.f;
#pragma unroll 8
        for (int kk = 0; kk < 32; ++kk)
            p = fmaf(s_h2[wk * 32 + kk], wr[kk], p);
        red[wk][lane] = p;
        __syncthreads();
        if (wk == 0) {
            float s = b3v;
#pragma unroll
            for (int j = 0; j < 8; ++j) s += red[j][lane];
            g_table[g_vals[i] * HD + h] = s;
        }
        __syncthreads();
    }
}

// ---------------- k3: permute + fp16 weights ----------------
// word layout: [mat(3)][chunk64(4)][ks16(4)][ntp(16)][lane(32)][j(4)]
//   j word = half2{ w[k][n], w[k+1][n] },  nt = 2*ntp + (j>>1),
//   n = nt*8 + (lane>>2),  k = chunk*64 + ks*16 + (j&1)*8 + (lane&3)*2
__global__ void wprep_kernel(const float* __restrict__ w0,
                             const float* __restrict__ w1,
                             const float* __restrict__ w2) {
    int i = blockIdx.x * blockDim.x + threadIdx.x;
    if (i >= 3 * HD * HD / 2) return;
    int j    = i & 3;
    int lane = (i >> 2) & 31;
    int ntp  = (i >> 7) & 15;
    int ks   = (i >> 11) & 3;
    int ch   = (i >> 13) & 3;
    int mat  = i >> 15;
    int nt = 2 * ntp + (j >> 1);
    int n  = nt * 8 + (lane >> 2);
    int k  = ch * 64 + ks * 16 + (j & 1) * 8 + (lane & 3) * 2;
    const float* w = (mat == 0) ? w0 : (mat == 1) ? w1 : w2;
    g_whf[i] = h2u(w[k * HD + n], w[(k + 1) * HD + n]);
}

// ---------------- main kernel ----------------
__device__ __forceinline__ void load_wchunk(uint32_t sb, int buf, int t) {
    int tx = threadIdx.x;
    const uint32_t* src = g_whf + (size_t)t * 8192;
    uint32_t dst = sb + WB_OFF + buf * WB_STRIDE;
#pragma unroll
    for (int it = 0; it < 8; ++it) {
        int u = it * 256 + tx;
        CP_ASYNC16(dst + u * 16, src + u * 4);
    }
    CP_COMMIT();
}

template <int RELU, int TAB>
__device__ __forceinline__ void epilogue(uint32_t sb, float acc[4][8][4],
                                         const float* __restrict__ bias,
                                         const int* __restrict__ s_tbl,
                                         float beta, int wm, int wn, int lane) {
    int q = lane & 3, gid = lane >> 2;
#pragma unroll
    for (int mt = 0; mt < 4; ++mt) {
        int r0 = wm * 64 + mt * 16 + gid;
        int trow0 = 0, trow1 = 0;
        if (TAB) { trow0 = s_tbl[r0]; trow1 = s_tbl[r0 + 8]; }
#pragma unroll
        for (int nt = 0; nt < 8; ++nt) {
            int colb = wn * 64 + nt * 8 + 2 * q;
            float2 bv = *(const float2*)(bias + colb);
            float v0 = acc[mt][nt][0] + bv.x;
            float v1 = acc[mt][nt][1] + bv.y;
            float v2 = acc[mt][nt][2] + bv.x;
            float v3 = acc[mt][nt][3] + bv.y;
            if (TAB) {
                float2 t0 = __ldg((const float2*)(g_table + trow0 + colb));
                float2 t1 = __ldg((const float2*)(g_table + trow1 + colb));
                v0 = fmaf(beta, t0.x, v0); v1 = fmaf(beta, t0.y, v1);
                v2 = fmaf(beta, t1.x, v2); v3 = fmaf(beta, t1.y, v3);
            }
            if (RELU) {
                v0 = fmaxf(v0, 0.f); v1 = fmaxf(v1, 0.f);
                v2 = fmaxf(v2, 0.f); v3 = fmaxf(v3, 0.f);
            }
            uint32_t a0 = sb + ACT_OFF + (uint32_t)(r0 * ASTRH + colb) * 2;
            sts32(a0, h2u(v0, v1));
            sts32(a0 + 8 * ASTRH * 2, h2u(v2, v3));
        }
    }
}

__global__ void __launch_bounds__(256, 1)
scn_mma_kernel(const float* __restrict__ x, const int* __restrict__ tar,
               const float* __restrict__ beta_p,
               const float* __restrict__ ijb1, const float* __restrict__ ijb2,
               const float* __restrict__ lb1,  const float* __restrict__ lw2,
               const float* __restrict__ lb2,  float* __restrict__ out, int E) {
    extern __shared__ char smem[];
    uint32_t sb = smem_u32(smem);
    int tx = threadIdx.x, w = tx >> 5, lane = tx & 31;
    int q = lane & 3, gid = lane >> 2;
    int wm = w & 1, wn = w >> 1;
    int e0 = blockIdx.x * BE;

    __shared__ int   s_src[BE], s_dst[BE], s_tbl[BE];
    __shared__ float s_red[BE];

    load_wchunk(sb, 0, 0);                 // prefetch chunk 0 under gather

    float* sbias = (float*)(smem + BIAS_OFF);
    for (int i = tx; i < 1024; i += 256) {
        float v;
        if      (i < 256) v = ijb1[i];
        else if (i < 512) v = ijb2[i - 256];
        else if (i < 768) v = lb1[i - 512];
        else              v = lw2[i - 768];
        sbias[i] = v;
    }
    if (tx < BE) {
        int e = e0 + tx; if (e >= E) e = E - 1;
        s_src[tx] = tar[e];
        s_dst[tx] = tar[E + e];
        s_tbl[tx] = g_counts[e] * HD;
        s_red[tx] = 0.f;
    }
    __syncthreads();

    float beta = *beta_p;
    float lb2v = *lb2;

    // ---- gather: A = fp16(xi * xj), row-major stride ASTRH ----
#pragma unroll 4
    for (int it = 0; it < 16; ++it) {
        int i = it * 256 + tx;             // 4096 8-half slots
        int m = i >> 5, c8 = i & 31;
        const float4* xa = (const float4*)(x + (size_t)s_src[m] * HD);
        const float4* xb = (const float4*)(x + (size_t)s_dst[m] * HD);
        float4 a0 = xa[2 * c8],     b0 = xb[2 * c8];
        float4 a1 = xa[2 * c8 + 1], b1 = xb[2 * c8 + 1];
        sts128(sb + ACT_OFF + (uint32_t)(m * ASTRH + c8 * 8) * 2,
               h2u(a0.x * b0.x, a0.y * b0.y), h2u(a0.z * b0.z, a0.w * b0.w),
               h2u(a1.x * b1.x, a1.y * b1.y), h2u(a1.z * b1.z, a1.w * b1.w));
    }

    // per-lane ldmatrix row base: row = wm*64 + (lane&7) + 8*((lane>>3)&1),
    // k half-offset 8*(lane>>4)
    uint32_t arow = (uint32_t)(wm * 64 + (lane & 7) + 8 * ((lane >> 3) & 1));
    uint32_t abase = sb + ACT_OFF + (arow * ASTRH + 8 * (uint32_t)(lane >> 4)) * 2;

    float acc[4][8][4];

#pragma unroll 1
    for (int t = 0; t < 12; ++t) {
        int c = t & 3, g = t >> 2;
        CP_WAIT0();
        __syncthreads();
        if (t + 1 < 12) load_wchunk(sb, (t + 1) & 1, t + 1);
        if (c == 0) {
#pragma unroll
            for (int mt = 0; mt < 4; ++mt)
#pragma unroll
                for (int nt = 0; nt < 8; ++nt)
#pragma unroll
                    for (int i = 0; i < 4; ++i) acc[mt][nt][i] = 0.f;
        }

        uint32_t bbase = sb + WB_OFF + (t & 1) * WB_STRIDE
                       + (uint32_t)(wn * 4) * 512 + lane * 16;
#pragma unroll
        for (int ks = 0; ks < 4; ++ks) {
            int kst = c * 4 + ks;                   // 16-K step within GEMM
            uint32_t a[4][4];
#pragma unroll
            for (int mt = 0; mt < 4; ++mt)
                ldmx4(a[mt], abase + (uint32_t)(mt * 16 * ASTRH + kst * 16) * 2);
            uint32_t bv[4][4];
#pragma unroll
            for (int p = 0; p < 4; ++p)
                lds128(bv[p], bbase + (uint32_t)(ks * 8192 + p * 512));
#pragma unroll
            for (int mt = 0; mt < 4; ++mt)
#pragma unroll
                for (int p = 0; p < 4; ++p) {
                    mma16(acc[mt][2 * p],     a[mt], bv[p][0], bv[p][1]);
                    mma16(acc[mt][2 * p + 1], a[mt], bv[p][2], bv[p][3]);
                }
        }

        if (c == 3) {
            __syncthreads();               // all MMAs done reading ACT
            if (g == 0) {
                epilogue<1, 0>(sb, acc, sbias,       s_tbl, beta, wm, wn, lane);
            } else if (g == 1) {
                epilogue<0, 1>(sb, acc, sbias + 256, s_tbl, beta, wm, wn, lane);
            } else {
#pragma unroll
                for (int mt = 0; mt < 4; ++mt) {
                    float p0 = 0.f, p1 = 0.f;
#pragma unroll
                    for (int nt = 0; nt < 8; ++nt) {
                        int colb = wn * 64 + nt * 8 + 2 * q;
                        float2 lb = *(const float2*)(sbias + 512 + colb);
                        float2 lw = *(const float2*)(sbias + 768 + colb);
                        p0 = fmaf(fmaxf(acc[mt][nt][0] + lb.x, 0.f), lw.x, p0);
                        p0 = fmaf(fmaxf(acc[mt][nt][1] + lb.y, 0.f), lw.y, p0);
                        p1 = fmaf(fmaxf(acc[mt][nt][2] + lb.x, 0.f), lw.x, p1);
                        p1 = fmaf(fmaxf(acc[mt][nt][3] + lb.y, 0.f), lw.y, p1);
                    }
                    p0 += __shfl_xor_sync(0xffffffffu, p0, 1);
                    p0 += __shfl_xor_sync(0xffffffffu, p0, 2);
                    p1 += __shfl_xor_sync(0xffffffffu, p1, 1);
                    p1 += __shfl_xor_sync(0xffffffffu, p1, 2);
                    if (q == 0) {
                        int r0 = wm * 64 + mt * 16 + gid;
                        atomicAdd(&s_red[r0],     p0);
                        atomicAdd(&s_red[r0 + 8], p1);
                    }
                }
            }
        }
    }

    __syncthreads();
    if (tx < BE && e0 + tx < E) out[e0 + tx] = s_red[tx] + lb2v;
}

// ---------------------------------------------------------------------------
extern "C" void kernel_launch(void* const* d_in, const int* in_sizes, int n_in,
                              void* d_out, int out_size) {
    const float* x    = (const float*)d_in[0];
    const int*   nbr  = (const int*)d_in[1];
    const int*   tar  = (const int*)d_in[2];
    const float* beta = (const float*)d_in[3];
    const float* cw1  = (const float*)d_in[4];
    const float* cb1  = (const float*)d_in[5];
    const float* cw2  = (const float*)d_in[6];
    const float* cb2  = (const float*)d_in[7];
    const float* cw3  = (const float*)d_in[8];
    const float* cb3  = (const float*)d_in[9];
    const float* ijw1 = (const float*)d_in[10];
    const float* ijb1 = (const float*)d_in[11];
    const float* ijw2 = (const float*)d_in[12];
    const float* ijb2 = (const float*)d_in[13];
    const float* lw1  = (const float*)d_in[14];
    const float* lb1  = (const float*)d_in[15];
    const float* lw2  = (const float*)d_in[16];
    const float* lb2  = (const float*)d_in[17];
    float* out = (float*)d_out;

    int E = in_sizes[2] / 2;
    if (E > MAXE) E = MAXE;

    cudaFuncSetAttribute(scn_mma_kernel,
                         cudaFuncAttributeMaxDynamicSharedMemorySize, SMEM_SZ);

    clear_flags_kernel<<<(NCOUNT + 255) / 256, 256>>>();
    wprep_kernel<<<(3 * HD * HD / 2 + 255) / 256, 256>>>(ijw1, ijw2, lw1);
    cn_count_kernel<<<(E + 7) / 8, 256>>>(nbr, tar, E);
    table_l2_kernel<<<8, 256>>>(cw1, cb1, cw2, cb2);
    table_l3_kernel<<<8, 256>>>(cw3, cb3);
    scn_mma_kernel<<<(E + BE - 1) / BE, 256, SMEM_SZ>>>(
        x, tar, beta, ijb1, ijb2, lb1, lw2, lb2, out, E);
}

// round 9
// speedup vs baseline: 2.5603x; 1.1150x over previous
#include <cuda_runtime.h>
#include <cuda_fp16.h>
#include <cuda_bf16.h>
#include <cstdint>

// ---------------------------------------------------------------------------
// SCNLinkPredictor — fp16 mma.sync m16n8k16, BE=64, 2 CTAs/SM.
//  k0 wprep(+clear) | k1 CN counts (+compaction) | k2a/k2b CN-MLP table
//  k3 main: 64 edges/CTA, 8 warps (2M x 4N), A row-major fp16 (stride 264),
//     W streamed in 32-K pieces (2-deep 16KB ring), ldmatrix A fragments,
//     3 chained GEMMs + fused epilogues. 2 CTAs/SM hide sync/epilogue bubbles.
// ---------------------------------------------------------------------------

#define MAXE   131072
#define HD     256
#define NCOUNT 4097
#define BE     64
#define ASTRH  264              // A row stride in halves

__device__ int g_counts[MAXE];
__device__ int g_flags[NCOUNT];
__device__ int g_vals[NCOUNT];
__device__ int g_nvals;
__device__ __align__(16) float    g_table[NCOUNT * HD];
__device__ __align__(16) float    g_h2[NCOUNT * HD];
__device__ __align__(16) uint32_t g_whf[3 * HD * HD / 2];  // permuted fp16 W

// ---------------- SMEM layout (dynamic, per CTA) ----------------
#define ACT_OFF   0                        // 64 x 264 halves = 33792 B
#define WB_OFF    33792                    // 2 ring buffers x 16384 B
#define WB_STRIDE 16384
#define BIAS_OFF  (WB_OFF + 2 * WB_STRIDE) // 66560: [b1|b2|lb1|lw2] f32
#define SMEM_SZ   (BIAS_OFF + 4096)        // 70656

// ---------------- PTX helpers ----------------
__device__ __forceinline__ uint32_t smem_u32(const void* p) {
    uint32_t a;
    asm("{ .reg .u64 t; cvta.to.shared.u64 t, %1; cvt.u32.u64 %0, t; }"
        : "=r"(a) : "l"(p));
    return a;
}
__device__ __forceinline__ void mma16(float* c, const uint32_t* a,
                                      uint32_t b0, uint32_t b1) {
    asm volatile(
        "mma.sync.aligned.m16n8k16.row.col.f32.f16.f16.f32 "
        "{%0,%1,%2,%3}, {%4,%5,%6,%7}, {%8,%9}, {%0,%1,%2,%3};"
        : "+f"(c[0]), "+f"(c[1]), "+f"(c[2]), "+f"(c[3])
        : "r"(a[0]), "r"(a[1]), "r"(a[2]), "r"(a[3]), "r"(b0), "r"(b1));
}
__device__ __forceinline__ void ldmx4(uint32_t* v, uint32_t addr) {
    asm volatile("ldmatrix.sync.aligned.m8n8.x4.shared.b16 {%0,%1,%2,%3}, [%4];"
                 : "=r"(v[0]), "=r"(v[1]), "=r"(v[2]), "=r"(v[3]) : "r"(addr));
}
__device__ __forceinline__ void lds128(uint32_t* v, uint32_t addr) {
    asm volatile("ld.shared.v4.b32 {%0,%1,%2,%3}, [%4];"
                 : "=r"(v[0]), "=r"(v[1]), "=r"(v[2]), "=r"(v[3]) : "r"(addr));
}
__device__ __forceinline__ void sts32(uint32_t addr, uint32_t v) {
    asm volatile("st.shared.b32 [%0], %1;" :: "r"(addr), "r"(v));
}
__device__ __forceinline__ void sts128(uint32_t addr, uint32_t v0, uint32_t v1,
                                       uint32_t v2, uint32_t v3) {
    asm volatile("st.shared.v4.b32 [%0], {%1,%2,%3,%4};"
                 :: "r"(addr), "r"(v0), "r"(v1), "r"(v2), "r"(v3));
}
__device__ __forceinline__ uint32_t h2u(float lo, float hi) {
    __half2 h = __floats2half2_rn(lo, hi);
    return *(uint32_t*)&h;
}
#define CP_ASYNC16(dst, src) \
    asm volatile("cp.async.cg.shared.global [%0], [%1], 16;" :: "r"(dst), "l"(src))
#define CP_COMMIT() asm volatile("cp.async.commit_group;" ::: "memory")
#define CP_WAIT0()  asm volatile("cp.async.wait_group 0;" ::: "memory")

// ---------------- k0: weight permute -> fp16 (+ flag clear, fused) ----------
// word layout: [mat(3)][chunk64(4)][ks16(4)][ntp(16)][lane(32)][j(4)]
//   j word = half2{ w[k][n], w[k+1][n] },  nt = 2*ntp + (j>>1),
//   n = nt*8 + (lane>>2),  k = chunk*64 + ks*16 + (j&1)*8 + (lane&3)*2
__global__ void wprep_kernel(const float* __restrict__ w0,
                             const float* __restrict__ w1,
                             const float* __restrict__ w2) {
    int i = blockIdx.x * blockDim.x + threadIdx.x;
    if (i < NCOUNT) g_flags[i] = 0;
    if (i == 0) g_nvals = 0;
    if (i >= 3 * HD * HD / 2) return;
    int j    = i & 3;
    int lane = (i >> 2) & 31;
    int ntp  = (i >> 7) & 15;
    int ks   = (i >> 11) & 3;
    int ch   = (i >> 13) & 3;
    int mat  = i >> 15;
    int nt = 2 * ntp + (j >> 1);
    int n  = nt * 8 + (lane >> 2);
    int k  = ch * 64 + ks * 16 + (j & 1) * 8 + (lane & 3) * 2;
    const float* w = (mat == 0) ? w0 : (mat == 1) ? w1 : w2;
    g_whf[i] = h2u(w[k * HD + n], w[(k + 1) * HD + n]);
}

// ---------------- k1: CN counts + compaction ----------------
__global__ void cn_count_kernel(const int* __restrict__ nbr,
                                const int* __restrict__ tar, int E) {
    int w = (blockIdx.x * blockDim.x + threadIdx.x) >> 5;
    int lane = threadIdx.x & 31;
    if (w >= E) return;
    int s = tar[w];
    int d = tar[E + w];
    int2 a = ((const int2*)(nbr + (size_t)s * 64))[lane];
    int2 b = ((const int2*)(nbr + (size_t)d * 64))[lane];
    int cnt = 0;
#pragma unroll
    for (int j = 0; j < 32; j++) {
        int v0 = __shfl_sync(0xffffffffu, b.x, j);
        int v1 = __shfl_sync(0xffffffffu, b.y, j);
        cnt += (a.x == v0) + (a.y == v0) + (a.x == v1) + (a.y == v1);
    }
#pragma unroll
    for (int off = 16; off; off >>= 1)
        cnt += __shfl_xor_sync(0xffffffffu, cnt, off);
    if (lane == 0) {
        g_counts[w] = cnt;
        if (atomicExch(&g_flags[cnt], 1) == 0) {
            int idx = atomicAdd(&g_nvals, 1);
            g_vals[idx] = cnt;
        }
    }
}

// ---------------- k2a: table layer 2 ----------------
__global__ void table_l2_kernel(const float* __restrict__ w1, const float* __restrict__ b1,
                                const float* __restrict__ w2, const float* __restrict__ b2) {
    __shared__ float s_w1[HD], s_b1[HD];
    __shared__ float red[8][33];
    int tx = threadIdx.x, lane = tx & 31, wk = tx >> 5;
    int h = blockIdx.x * 32 + lane;
    for (int i = tx; i < HD; i += 256) { s_w1[i] = w1[i]; s_b1[i] = b1[i]; }
    float wr[32];
#pragma unroll 8
    for (int kk = 0; kk < 32; ++kk)
        wr[kk] = w2[(wk * 32 + kk) * HD + h];
    __syncthreads();
    int nv = g_nvals;
    float b2v = b2[h];
    for (int i = 0; i < nv; ++i) {
        float cf = (float)g_vals[i];
        float p = 0.f;
#pragma unroll 8
        for (int kk = 0; kk < 32; ++kk) {
            int k = wk * 32 + kk;
            p = fmaf(fmaxf(fmaf(cf, s_w1[k], s_b1[k]), 0.f), wr[kk], p);
        }
        red[wk][lane] = p;
        __syncthreads();
        if (wk == 0) {
            float s = b2v;
#pragma unroll
            for (int j = 0; j < 8; ++j) s += red[j][lane];
            g_h2[i * HD + h] = fmaxf(s, 0.f);
        }
        __syncthreads();
    }
}

// ---------------- k2b: table layer 3 ----------------
__global__ void table_l3_kernel(const float* __restrict__ w3, const float* __restrict__ b3) {
    __shared__ float red[8][33];
    __shared__ float s_h2[HD];
    int tx = threadIdx.x, lane = tx & 31, wk = tx >> 5;
    int h = blockIdx.x * 32 + lane;
    float wr[32];
#pragma unroll 8
    for (int kk = 0; kk < 32; ++kk)
        wr[kk] = w3[(wk * 32 + kk) * HD + h];
    int nv = g_nvals;
    float b3v = b3[h];
    for (int i = 0; i < nv; ++i) {
        for (int j = tx; j < HD; j += 256) s_h2[j] = g_h2[i * HD + j];
        __syncthreads();
        float p = 0.f;
#pragma unroll 8
        for (int kk = 0; kk < 32; ++kk)
            p = fmaf(s_h2[wk * 32 + kk], wr[kk], p);
        red[wk][lane] = p;
        __syncthreads();
        if (wk == 0) {
            float s = b3v;
#pragma unroll
            for (int j = 0; j < 8; ++j) s += red[j][lane];
            g_table[g_vals[i] * HD + h] = s;
        }
        __syncthreads();
    }
}

// ---------------- main kernel ----------------
// stream one 32-K piece (16 KB): piece t in [0,24), src word offset t*4096
__device__ __forceinline__ void load_wpiece(uint32_t sb, int buf, int t) {
    int tx = threadIdx.x;
    const uint32_t* src = g_whf + (size_t)t * 4096;
    uint32_t dst = sb + WB_OFF + buf * WB_STRIDE;
#pragma unroll
    for (int it = 0; it < 4; ++it) {
        int u = it * 256 + tx;
        CP_ASYNC16(dst + u * 16, src + u * 4);
    }
    CP_COMMIT();
}

template <int RELU, int TAB>
__device__ __forceinline__ void epilogue(uint32_t sb, float acc[2][8][4],
                                         const float* __restrict__ bias,
                                         const int* __restrict__ s_tbl,
                                         float beta, int wm, int wn, int lane) {
    int q = lane & 3, gid = lane >> 2;
#pragma unroll
    for (int mt = 0; mt < 2; ++mt) {
        int r0 = wm * 32 + mt * 16 + gid;
        int trow0 = 0, trow1 = 0;
        if (TAB) { trow0 = s_tbl[r0]; trow1 = s_tbl[r0 + 8]; }
#pragma unroll
        for (int nt = 0; nt < 8; ++nt) {
            int colb = wn * 64 + nt * 8 + 2 * q;
            float2 bv = *(const float2*)(bias + colb);
            float v0 = acc[mt][nt][0] + bv.x;
            float v1 = acc[mt][nt][1] + bv.y;
            float v2 = acc[mt][nt][2] + bv.x;
            float v3 = acc[mt][nt][3] + bv.y;
            if (TAB) {
                float2 t0 = __ldg((const float2*)(g_table + trow0 + colb));
                float2 t1 = __ldg((const float2*)(g_table + trow1 + colb));
                v0 = fmaf(beta, t0.x, v0); v1 = fmaf(beta, t0.y, v1);
                v2 = fmaf(beta, t1.x, v2); v3 = fmaf(beta, t1.y, v3);
            }
            if (RELU) {
                v0 = fmaxf(v0, 0.f); v1 = fmaxf(v1, 0.f);
                v2 = fmaxf(v2, 0.f); v3 = fmaxf(v3, 0.f);
            }
            uint32_t a0 = sb + ACT_OFF + (uint32_t)(r0 * ASTRH + colb) * 2;
            sts32(a0, h2u(v0, v1));
            sts32(a0 + 8 * ASTRH * 2, h2u(v2, v3));
        }
    }
}

__global__ void __launch_bounds__(256, 2)
scn_mma_kernel(const float* __restrict__ x, const int* __restrict__ tar,
               const float* __restrict__ beta_p,
               const float* __restrict__ ijb1, const float* __restrict__ ijb2,
               const float* __restrict__ lb1,  const float* __restrict__ lw2,
               const float* __restrict__ lb2,  float* __restrict__ out, int E) {
    extern __shared__ char smem[];
    uint32_t sb = smem_u32(smem);
    int tx = threadIdx.x, w = tx >> 5, lane = tx & 31;
    int q = lane & 3, gid = lane >> 2;
    int wm = w & 1, wn = w >> 1;            // 2 M-groups x 4 N-groups
    int e0 = blockIdx.x * BE;

    __shared__ int   s_src[BE], s_dst[BE], s_tbl[BE];
    __shared__ float s_red[BE];

    load_wpiece(sb, 0, 0);                  // prefetch piece 0 under gather

    float* sbias = (float*)(smem + BIAS_OFF);
    for (int i = tx; i < 1024; i += 256) {
        float v;
        if      (i < 256) v = ijb1[i];
        else if (i < 512) v = ijb2[i - 256];
        else if (i < 768) v = lb1[i - 512];
        else              v = lw2[i - 768];
        sbias[i] = v;
    }
    if (tx < BE) {
        int e = e0 + tx; if (e >= E) e = E - 1;
        s_src[tx] = tar[e];
        s_dst[tx] = tar[E + e];
        s_tbl[tx] = g_counts[e] * HD;
        s_red[tx] = 0.f;
    }
    __syncthreads();

    float beta = *beta_p;
    float lb2v = *lb2;

    // ---- gather: A = fp16(xi * xj), row-major stride ASTRH ----
#pragma unroll 4
    for (int it = 0; it < 8; ++it) {
        int i = it * 256 + tx;              // 2048 8-half slots
        int m = i >> 5, c8 = i & 31;
        const float4* xa = (const float4*)(x + (size_t)s_src[m] * HD);
        const float4* xb = (const float4*)(x + (size_t)s_dst[m] * HD);
        float4 a0 = xa[2 * c8],     b0 = xb[2 * c8];
        float4 a1 = xa[2 * c8 + 1], b1 = xb[2 * c8 + 1];
        sts128(sb + ACT_OFF + (uint32_t)(m * ASTRH + c8 * 8) * 2,
               h2u(a0.x * b0.x, a0.y * b0.y), h2u(a0.z * b0.z, a0.w * b0.w),
               h2u(a1.x * b1.x, a1.y * b1.y), h2u(a1.z * b1.z, a1.w * b1.w));
    }

    // ldmatrix lane base: row = wm*32 + (lane&7) + 8*((lane>>3)&1),
    // k half-offset 8*(lane>>4)
    uint32_t arow = (uint32_t)(wm * 32 + (lane & 7) + 8 * ((lane >> 3) & 1));
    uint32_t abase = sb + ACT_OFF + (arow * ASTRH + 8 * (uint32_t)(lane >> 4)) * 2;

    float acc[2][8][4];

#pragma unroll 1
    for (int t = 0; t < 24; ++t) {
        int c = t & 7, g = t >> 3;
        CP_WAIT0();
        __syncthreads();
        if (t + 1 < 24) load_wpiece(sb, (t + 1) & 1, t + 1);
        if (c == 0) {
#pragma unroll
            for (int mt = 0; mt < 2; ++mt)
#pragma unroll
                for (int nt = 0; nt < 8; ++nt)
#pragma unroll
                    for (int i = 0; i < 4; ++i) acc[mt][nt][i] = 0.f;
        }

        uint32_t bbase = sb + WB_OFF + (t & 1) * WB_STRIDE
                       + (uint32_t)(wn * 4) * 512 + lane * 16;
#pragma unroll
        for (int ks = 0; ks < 2; ++ks) {
            int kst = c * 2 + ks;                   // 16-K step within GEMM
            uint32_t a[2][4];
#pragma unroll
            for (int mt = 0; mt < 2; ++mt)
                ldmx4(a[mt], abase + (uint32_t)(mt * 16 * ASTRH + kst * 16) * 2);
            uint32_t bv[4][4];
#pragma unroll
            for (int p = 0; p < 4; ++p)
                lds128(bv[p], bbase + (uint32_t)(ks * 8192 + p * 512));
#pragma unroll
            for (int mt = 0; mt < 2; ++mt)
#pragma unroll
                for (int p = 0; p < 4; ++p) {
                    mma16(acc[mt][2 * p],     a[mt], bv[p][0], bv[p][1]);
                    mma16(acc[mt][2 * p + 1], a[mt], bv[p][2], bv[p][3]);
                }
        }

        if (c == 7) {
            __syncthreads();                // all MMAs done reading ACT
            if (g == 0) {
                epilogue<1, 0>(sb, acc, sbias,       s_tbl, beta, wm, wn, lane);
            } else if (g == 1) {
                epilogue<0, 1>(sb, acc, sbias + 256, s_tbl, beta, wm, wn, lane);
            } else {
                // final: out = relu(C + lb1) . lw2 + lb2, folded in fragments
#pragma unroll
                for (int mt = 0; mt < 2; ++mt) {
                    float p0 = 0.f, p1 = 0.f;
#pragma unroll
                    for (int nt = 0; nt < 8; ++nt) {
                        int colb = wn * 64 + nt * 8 + 2 * q;
                        float2 lb = *(const float2*)(sbias + 512 + colb);
                        float2 lw = *(const float2*)(sbias + 768 + colb);
                        p0 = fmaf(fmaxf(acc[mt][nt][0] + lb.x, 0.f), lw.x, p0);
                        p0 = fmaf(fmaxf(acc[mt][nt][1] + lb.y, 0.f), lw.y, p0);
                        p1 = fmaf(fmaxf(acc[mt][nt][2] + lb.x, 0.f), lw.x, p1);
                        p1 = fmaf(fmaxf(acc[mt][nt][3] + lb.y, 0.f), lw.y, p1);
                    }
                    p0 += __shfl_xor_sync(0xffffffffu, p0, 1);
                    p0 += __shfl_xor_sync(0xffffffffu, p0, 2);
                    p1 += __shfl_xor_sync(0xffffffffu, p1, 1);
                    p1 += __shfl_xor_sync(0xffffffffu, p1, 2);
                    if (q == 0) {
                        int r0 = wm * 32 + mt * 16 + gid;
                        atomicAdd(&s_red[r0],     p0);
                        atomicAdd(&s_red[r0 + 8], p1);
                    }
                }
            }
        }
    }

    __syncthreads();
    if (tx < BE && e0 + tx < E) out[e0 + tx] = s_red[tx] + lb2v;
}

// ---------------------------------------------------------------------------
extern "C" void kernel_launch(void* const* d_in, const int* in_sizes, int n_in,
                              void* d_out, int out_size) {
    const float* x    = (const float*)d_in[0];
    const int*   nbr  = (const int*)d_in[1];
    const int*   tar  = (const int*)d_in[2];
    const float* beta = (const float*)d_in[3];
    const float* cw1  = (const float*)d_in[4];
    const float* cb1  = (const float*)d_in[5];
    const float* cw2  = (const float*)d_in[6];
    const float* cb2  = (const float*)d_in[7];
    const float* cw3  = (const float*)d_in[8];
    const float* cb3  = (const float*)d_in[9];
    const float* ijw1 = (const float*)d_in[10];
    const float* ijb1 = (const float*)d_in[11];
    const float* ijw2 = (const float*)d_in[12];
    const float* ijb2 = (const float*)d_in[13];
    const float* lw1  = (const float*)d_in[14];
    const float* lb1  = (const float*)d_in[15];
    const float* lw2  = (const float*)d_in[16];
    const float* lb2  = (const float*)d_in[17];
    float* out = (float*)d_out;

    int E = in_sizes[2] / 2;
    if (E > MAXE) E = MAXE;

    cudaFuncSetAttribute(scn_mma_kernel,
                         cudaFuncAttributeMaxDynamicSharedMemorySize, SMEM_SZ);

    wprep_kernel<<<(3 * HD * HD / 2 + 255) / 256, 256>>>(ijw1, ijw2, lw1);
    cn_count_kernel<<<(E + 7) / 8, 256>>>(nbr, tar, E);
    table_l2_kernel<<<8, 256>>>(cw1, cb1, cw2, cb2);
    table_l3_kernel<<<8, 256>>>(cw3, cb3);
    scn_mma_kernel<<<(E + BE - 1) / BE, 256, SMEM_SZ>>>(
        x, tar, beta, ijb1, ijb2, lb1, lw2, lb2, out, E);
}

// round 12
// speedup vs baseline: 2.7779x; 1.0850x over previous
#include <cuda_runtime.h>
#include <cuda_fp16.h>
#include <cuda_bf16.h>
#include <cstdint>

// ---------------------------------------------------------------------------
// SCNLinkPredictor — fp16 mma.sync m16n8k16, BE=64, 2 CTAs/SM,
// per-warp-pair weight rings (named-barrier sync, no block sync in mainloop).
//
//  k0: fused [weight permute->fp16 | CN counts + compaction]
//  k1: fused CN-MLP table (layer2 + spin-barrier + layer3), 8 blocks
//  k2: main: 64 edges/CTA, 8 warps (2M x 4N). A row-major fp16 (stride 264).
//      B streamed per warp-pair: 4-deep 4KB ring, each warp loads its half,
//      cp.async.wait_group + bar.sync(pair,64). Block syncs only at GEMM
//      boundaries. Tail: clear flags for next replay.
//  R11 fix vs R10: restored the __syncthreads() between shared-init and the
//      gather loop (its absence made all warps read uninitialized s_src/s_dst).
// ---------------------------------------------------------------------------

#define MAXE   131072
#define HD     256
#define NCOUNT 4097
#define BE     64
#define ASTRH  264              // A row stride in halves

__device__ int g_counts[MAXE];
__device__ int g_flags[NCOUNT];
__device__ int g_vals[NCOUNT];
__device__ int g_nvals;
__device__ int g_arrive;
__device__ __align__(16) float    g_table[NCOUNT * HD];
__device__ __align__(16) float    g_h2[NCOUNT * HD];
__device__ __align__(16) uint32_t g_whf[3 * HD * HD / 2];  // permuted fp16 W

// ---------------- SMEM layout (dynamic, per CTA) ----------------
#define ACT_OFF   0                        // 64 x 264 halves = 33792 B
#define WB_OFF    33792                    // 4 pairs x 4 bufs x 4KB = 65536 B
#define BIAS_OFF  (WB_OFF + 65536)         // 99328: [b1|b2|lb1|lw2] f32
#define SMEM_SZ   (BIAS_OFF + 4096)        // 103424

// ---------------- PTX helpers ----------------
__device__ __forceinline__ uint32_t smem_u32(const void* p) {
    uint32_t a;
    asm("{ .reg .u64 t; cvta.to.shared.u64 t, %1; cvt.u32.u64 %0, t; }"
        : "=r"(a) : "l"(p));
    return a;
}
__device__ __forceinline__ void mma16(float* c, const uint32_t* a,
                                      uint32_t b0, uint32_t b1) {
    asm volatile(
        "mma.sync.aligned.m16n8k16.row.col.f32.f16.f16.f32 "
        "{%0,%1,%2,%3}, {%4,%5,%6,%7}, {%8,%9}, {%0,%1,%2,%3};"
        : "+f"(c[0]), "+f"(c[1]), "+f"(c[2]), "+f"(c[3])
        : "r"(a[0]), "r"(a[1]), "r"(a[2]), "r"(a[3]), "r"(b0), "r"(b1));
}
__device__ __forceinline__ void ldmx4(uint32_t* v, uint32_t addr) {
    asm volatile("ldmatrix.sync.aligned.m8n8.x4.shared.b16 {%0,%1,%2,%3}, [%4];"
                 : "=r"(v[0]), "=r"(v[1]), "=r"(v[2]), "=r"(v[3]) : "r"(addr));
}
__device__ __forceinline__ void lds128(uint32_t* v, uint32_t addr) {
    asm volatile("ld.shared.v4.b32 {%0,%1,%2,%3}, [%4];"
                 : "=r"(v[0]), "=r"(v[1]), "=r"(v[2]), "=r"(v[3]) : "r"(addr));
}
__device__ __forceinline__ void sts32(uint32_t addr, uint32_t v) {
    asm volatile("st.shared.b32 [%0], %1;" :: "r"(addr), "r"(v));
}
__device__ __forceinline__ void sts128(uint32_t addr, uint32_t v0, uint32_t v1,
                                       uint32_t v2, uint32_t v3) {
    asm volatile("st.shared.v4.b32 [%0], {%1,%2,%3,%4};"
                 :: "r"(addr), "r"(v0), "r"(v1), "r"(v2), "r"(v3));
}
__device__ __forceinline__ uint32_t h2u(float lo, float hi) {
    __half2 h = __floats2half2_rn(lo, hi);
    return *(uint32_t*)&h;
}
#define CP_ASYNC16(dst, src) \
    asm volatile("cp.async.cg.shared.global [%0], [%1], 16;" :: "r"(dst), "l"(src))
#define CP_COMMIT() asm volatile("cp.async.commit_group;" ::: "memory")
#define CP_WAIT(n)  asm volatile("cp.async.wait_group %0;" :: "n"(n) : "memory")
#define BAR_PAIR(id) \
    asm volatile("bar.sync %0, 64;" :: "r"(id) : "memory")

// ---------------- k0: fused wprep + cn_count ----------------
// wprep word layout (i):
//   j=i&3, lane=(i>>2)&31, ntw=(i>>7)&3, ks=(i>>9)&1, wn=(i>>10)&3,
//   p=(i>>12)&7, mat=i>>15
//   nt = 2*(wn*4+ntw)+(j>>1); n = nt*8+(lane>>2)
//   k  = p*32 + ks*16 + (j&1)*8 + (lane&3)*2
#define WPREP_BLOCKS 384       // 384*256 = 98304 = 3*HD*HD/2
__global__ void prep_kernel(const float* __restrict__ w0,
                            const float* __restrict__ w1,
                            const float* __restrict__ w2,
                            const int* __restrict__ nbr,
                            const int* __restrict__ tar, int E) {
    if (blockIdx.x < WPREP_BLOCKS) {
        int i = blockIdx.x * 256 + threadIdx.x;
        int j    = i & 3;
        int lane = (i >> 2) & 31;
        int ntw  = (i >> 7) & 3;
        int ks   = (i >> 9) & 1;
        int wn   = (i >> 10) & 3;
        int p    = (i >> 12) & 7;
        int mat  = i >> 15;
        int nt = 2 * (wn * 4 + ntw) + (j >> 1);
        int n  = nt * 8 + (lane >> 2);
        int k  = p * 32 + ks * 16 + (j & 1) * 8 + (lane & 3) * 2;
        const float* w = (mat == 0) ? w0 : (mat == 1) ? w1 : w2;
        g_whf[i] = h2u(w[k * HD + n], w[(k + 1) * HD + n]);
        return;
    }
    // ---- cn_count part ----
    int wid  = (blockIdx.x - WPREP_BLOCKS) * 8 + (threadIdx.x >> 5);
    int lane = threadIdx.x & 31;
    if (wid >= E) return;
    int s = tar[wid];
    int d = tar[E + wid];
    int2 a = ((const int2*)(nbr + (size_t)s * 64))[lane];
    int2 b = ((const int2*)(nbr + (size_t)d * 64))[lane];
    int cnt = 0;
#pragma unroll
    for (int j = 0; j < 32; j++) {
        int v0 = __shfl_sync(0xffffffffu, b.x, j);
        int v1 = __shfl_sync(0xffffffffu, b.y, j);
        cnt += (a.x == v0) + (a.y == v0) + (a.x == v1) + (a.y == v1);
    }
#pragma unroll
    for (int off = 16; off; off >>= 1)
        cnt += __shfl_xor_sync(0xffffffffu, cnt, off);
    if (lane == 0) {
        g_counts[wid] = cnt;
        if (atomicExch(&g_flags[cnt], 1) == 0) {
            int idx = atomicAdd(&g_nvals, 1);
            g_vals[idx] = cnt;
        }
    }
}

// ---------------- k1: fused table (l2 + spin barrier + l3) ----------------
__global__ void table_kernel(const float* __restrict__ w1, const float* __restrict__ b1,
                             const float* __restrict__ w2, const float* __restrict__ b2,
                             const float* __restrict__ w3, const float* __restrict__ b3) {
    __shared__ float s_w1[HD], s_b1[HD];
    __shared__ float red[8][33];
    __shared__ float s_h2[HD];
    int tx = threadIdx.x, lane = tx & 31, wk = tx >> 5;
    int h = blockIdx.x * 32 + lane;
    for (int i = tx; i < HD; i += 256) { s_w1[i] = w1[i]; s_b1[i] = b1[i]; }
    float wr2[32], wr3[32];
#pragma unroll 8
    for (int kk = 0; kk < 32; ++kk) {
        wr2[kk] = w2[(wk * 32 + kk) * HD + h];
        wr3[kk] = w3[(wk * 32 + kk) * HD + h];
    }
    __syncthreads();
    int nv = g_nvals;
    float b2v = b2[h], b3v = b3[h];

    // phase 1: h2 = relu(relu(c*w1+b1) @ w2 + b2)
    for (int i = 0; i < nv; ++i) {
        float cf = (float)g_vals[i];
        float p = 0.f;
#pragma unroll 8
        for (int kk = 0; kk < 32; ++kk) {
            int k = wk * 32 + kk;
            p = fmaf(fmaxf(fmaf(cf, s_w1[k], s_b1[k]), 0.f), wr2[kk], p);
        }
        red[wk][lane] = p;
        __syncthreads();
        if (wk == 0) {
            float s = b2v;
#pragma unroll
            for (int j = 0; j < 8; ++j) s += red[j][lane];
            g_h2[i * HD + h] = fmaxf(s, 0.f);
        }
        __syncthreads();
    }

    // grid spin barrier (8 blocks, all co-resident)
    __threadfence();
    __syncthreads();
    if (tx == 0) {
        atomicAdd(&g_arrive, 1);
        while (atomicAdd(&g_arrive, 0) < 8) { }
        __threadfence();
    }
    __syncthreads();

    // phase 2: table[c] = h2 @ w3 + b3
    for (int i = 0; i < nv; ++i) {
        for (int j = tx; j < HD; j += 256) s_h2[j] = __ldcg(&g_h2[i * HD + j]);
        __syncthreads();
        float p = 0.f;
#pragma unroll 8
        for (int kk = 0; kk < 32; ++kk)
            p = fmaf(s_h2[wk * 32 + kk], wr3[kk], p);
        red[wk][lane] = p;
        __syncthreads();
        if (wk == 0) {
            float s = b3v;
#pragma unroll
            for (int j = 0; j < 8; ++j) s += red[j][lane];
            g_table[g_vals[i] * HD + h] = s;
        }
        __syncthreads();
    }
}

// ---------------- main kernel ----------------
// issue this warp's half (2KB) of pair wn's piece t into ring buffer t&3
__device__ __forceinline__ void issue_piece(uint32_t sb, int t, int wn, int wm,
                                            int lane) {
    const uint32_t* src = g_whf + ((((size_t)t * 4 + wn) * 2 + wm) << 9) + lane * 4;
    uint32_t dst = sb + WB_OFF + wn * 16384 + (t & 3) * 4096 + wm * 2048 + lane * 16;
#pragma unroll
    for (int it = 0; it < 4; ++it)
        CP_ASYNC16(dst + it * 512, src + it * 128);
    CP_COMMIT();
}

template <int RELU, int TAB>
__device__ __forceinline__ void epilogue(uint32_t sb, float acc[2][8][4],
                                         const float* __restrict__ bias,
                                         const int* __restrict__ s_tbl,
                                         float beta, int wm, int wn, int lane) {
    int q = lane & 3, gid = lane >> 2;
#pragma unroll
    for (int mt = 0; mt < 2; ++mt) {
        int r0 = wm * 32 + mt * 16 + gid;
        int trow0 = 0, trow1 = 0;
        if (TAB) { trow0 = s_tbl[r0]; trow1 = s_tbl[r0 + 8]; }
#pragma unroll
        for (int nt = 0; nt < 8; ++nt) {
            int colb = wn * 64 + nt * 8 + 2 * q;
            float2 bv = *(const float2*)(bias + colb);
            float v0 = acc[mt][nt][0] + bv.x;
            float v1 = acc[mt][nt][1] + bv.y;
            float v2 = acc[mt][nt][2] + bv.x;
            float v3 = acc[mt][nt][3] + bv.y;
            if (TAB) {
                float2 t0 = __ldg((const float2*)(g_table + trow0 + colb));
                float2 t1 = __ldg((const float2*)(g_table + trow1 + colb));
                v0 = fmaf(beta, t0.x, v0); v1 = fmaf(beta, t0.y, v1);
                v2 = fmaf(beta, t1.x, v2); v3 = fmaf(beta, t1.y, v3);
            }
            if (RELU) {
                v0 = fmaxf(v0, 0.f); v1 = fmaxf(v1, 0.f);
                v2 = fmaxf(v2, 0.f); v3 = fmaxf(v3, 0.f);
            }
            uint32_t a0 = sb + ACT_OFF + (uint32_t)(r0 * ASTRH + colb) * 2;
            sts32(a0, h2u(v0, v1));
            sts32(a0 + 8 * ASTRH * 2, h2u(v2, v3));
        }
    }
}

__global__ void __launch_bounds__(256, 2)
scn_mma_kernel(const float* __restrict__ x, const int* __restrict__ tar,
               const float* __restrict__ beta_p,
               const float* __restrict__ ijb1, const float* __restrict__ ijb2,
               const float* __restrict__ lb1,  const float* __restrict__ lw2,
               const float* __restrict__ lb2,  float* __restrict__ out, int E) {
    extern __shared__ char smem[];
    uint32_t sb = smem_u32(smem);
    int tx = threadIdx.x, w = tx >> 5, lane = tx & 31;
    int q = lane & 3, gid = lane >> 2;
    int wm = w & 1, wn = w >> 1;            // pair id = wn (threads 64*wn..+63)
    int e0 = blockIdx.x * BE;

    __shared__ int   s_src[BE], s_dst[BE], s_tbl[BE];
    __shared__ float s_red[BE];

    // prefetch first 3 pieces into the pair ring
    issue_piece(sb, 0, wn, wm, lane);
    issue_piece(sb, 1, wn, wm, lane);
    issue_piece(sb, 2, wn, wm, lane);

    float* sbias = (float*)(smem + BIAS_OFF);
    for (int i = tx; i < 1024; i += 256) {
        float v;
        if      (i < 256) v = ijb1[i];
        else if (i < 512) v = ijb2[i - 256];
        else if (i < 768) v = lb1[i - 512];
        else              v = lw2[i - 768];
        sbias[i] = v;
    }
    if (tx < BE) {
        int e = e0 + tx; if (e >= E) e = E - 1;
        s_src[tx] = tar[e];
        s_dst[tx] = tar[E + e];
        s_tbl[tx] = g_counts[e] * HD;
        s_red[tx] = 0.f;
    }
    __syncthreads();            // R11 FIX: s_src/s_dst/s_tbl visible to all warps

    float beta = *beta_p;
    float lb2v = *lb2;

    // ---- gather: A = fp16(xi * xj), row-major stride ASTRH ----
#pragma unroll 4
    for (int it = 0; it < 8; ++it) {
        int i = it * 256 + tx;              // 2048 8-half slots
        int m = i >> 5, c8 = i & 31;
        const float4* xa = (const float4*)(x + (size_t)s_src[m] * HD);
        const float4* xb = (const float4*)(x + (size_t)s_dst[m] * HD);
        float4 a0 = xa[2 * c8],     b0 = xb[2 * c8];
        float4 a1 = xa[2 * c8 + 1], b1 = xb[2 * c8 + 1];
        sts128(sb + ACT_OFF + (uint32_t)(m * ASTRH + c8 * 8) * 2,
               h2u(a0.x * b0.x, a0.y * b0.y), h2u(a0.z * b0.z, a0.w * b0.w),
               h2u(a1.x * b1.x, a1.y * b1.y), h2u(a1.z * b1.z, a1.w * b1.w));
    }
    __syncthreads();

    // ldmatrix lane base
    uint32_t arow = (uint32_t)(wm * 32 + (lane & 7) + 8 * ((lane >> 3) & 1));
    uint32_t abase = sb + ACT_OFF + (arow * ASTRH + 8 * (uint32_t)(lane >> 4)) * 2;
    uint32_t wpair = sb + WB_OFF + wn * 16384;

    float acc[2][8][4];

#pragma unroll 1
    for (int t = 0; t < 24; ++t) {
        int c = t & 7, g = t >> 3;
        if (t < 22)      { CP_WAIT(2); }    // my half of piece t landed
        else if (t < 23) { CP_WAIT(1); }
        else             { CP_WAIT(0); }
        BAR_PAIR(wn + 1);                   // partner's half landed
        if (c == 0) {
#pragma unroll
            for (int mt = 0; mt < 2; ++mt)
#pragma unroll
                for (int nt = 0; nt < 8; ++nt)
#pragma unroll
                    for (int i = 0; i < 4; ++i) acc[mt][nt][i] = 0.f;
        }

        uint32_t bbuf = wpair + (uint32_t)(t & 3) * 4096;
#pragma unroll
        for (int ks = 0; ks < 2; ++ks) {
            int kst = c * 2 + ks;
            uint32_t a[2][4];
#pragma unroll
            for (int mt = 0; mt < 2; ++mt)
                ldmx4(a[mt], abase + (uint32_t)(mt * 16 * ASTRH + kst * 16) * 2);
            uint32_t bv[4][4];
            uint32_t bks = bbuf + ks * 2048 + lane * 16;
#pragma unroll
            for (int p = 0; p < 4; ++p)
                lds128(bv[p], bks + (uint32_t)(p * 512));
#pragma unroll
            for (int mt = 0; mt < 2; ++mt)
#pragma unroll
                for (int p = 0; p < 4; ++p) {
                    mma16(acc[mt][2 * p],     a[mt], bv[p][0], bv[p][1]);
                    mma16(acc[mt][2 * p + 1], a[mt], bv[p][2], bv[p][3]);
                }
        }

        if (t + 3 < 24) issue_piece(sb, t + 3, wn, wm, lane);

        if (c == 7) {
            __syncthreads();                // all warps done reading ACT
            if (g == 0) {
                epilogue<1, 0>(sb, acc, sbias,       s_tbl, beta, wm, wn, lane);
            } else if (g == 1) {
                epilogue<0, 1>(sb, acc, sbias + 256, s_tbl, beta, wm, wn, lane);
            } else {
                // final: out = relu(C + lb1) . lw2 + lb2
#pragma unroll
                for (int mt = 0; mt < 2; ++mt) {
                    float p0 = 0.f, p1 = 0.f;
#pragma unroll
                    for (int nt = 0; nt < 8; ++nt) {
                        int colb = wn * 64 + nt * 8 + 2 * q;
                        float2 lb = *(const float2*)(sbias + 512 + colb);
                        float2 lw = *(const float2*)(sbias + 768 + colb);
                        p0 = fmaf(fmaxf(acc[mt][nt][0] + lb.x, 0.f), lw.x, p0);
                        p0 = fmaf(fmaxf(acc[mt][nt][1] + lb.y, 0.f), lw.y, p0);
                        p1 = fmaf(fmaxf(acc[mt][nt][2] + lb.x, 0.f), lw.x, p1);
                        p1 = fmaf(fmaxf(acc[mt][nt][3] + lb.y, 0.f), lw.y, p1);
                    }
                    p0 += __shfl_xor_sync(0xffffffffu, p0, 1);
                    p0 += __shfl_xor_sync(0xffffffffu, p0, 2);
                    p1 += __shfl_xor_sync(0xffffffffu, p1, 1);
                    p1 += __shfl_xor_sync(0xffffffffu, p1, 2);
                    if (q == 0) {
                        int r0 = wm * 32 + mt * 16 + gid;
                        atomicAdd(&s_red[r0],     p0);
                        atomicAdd(&s_red[r0 + 8], p1);
                    }
                }
            }
            __syncthreads();                // epilogue writes visible
        }
    }

    if (tx < BE && e0 + tx < E) out[e0 + tx] = s_red[tx] + lb2v;

    // tail: clean global state for the next replay (globals start zeroed)
    if (blockIdx.x == 0) {
        for (int i = tx; i < NCOUNT; i += 256) g_flags[i] = 0;
        if (tx == 0) { g_nvals = 0; g_arrive = 0; }
    }
}

// ---------------------------------------------------------------------------
extern "C" void kernel_launch(void* const* d_in, const int* in_sizes, int n_in,
                              void* d_out, int out_size) {
    const float* x    = (const float*)d_in[0];
    const int*   nbr  = (const int*)d_in[1];
    const int*   tar  = (const int*)d_in[2];
    const float* beta = (const float*)d_in[3];
    const float* cw1  = (const float*)d_in[4];
    const float* cb1  = (const float*)d_in[5];
    const float* cw2  = (const float*)d_in[6];
    const float* cb2  = (const float*)d_in[7];
    const float* cw3  = (const float*)d_in[8];
    const float* cb3  = (const float*)d_in[9];
    const float* ijw1 = (const float*)d_in[10];
    const float* ijb1 = (const float*)d_in[11];
    const float* ijw2 = (const float*)d_in[12];
    const float* ijb2 = (const float*)d_in[13];
    const float* lw1  = (const float*)d_in[14];
    const float* lb1  = (const float*)d_in[15];
    const float* lw2  = (const float*)d_in[16];
    const float* lb2  = (const float*)d_in[17];
    float* out = (float*)d_out;

    int E = in_sizes[2] / 2;
    if (E > MAXE) E = MAXE;

    cudaFuncSetAttribute(scn_mma_kernel,
                         cudaFuncAttributeMaxDynamicSharedMemorySize, SMEM_SZ);

    int cn_blocks = (E + 7) / 8;
    prep_kernel<<<WPREP_BLOCKS + cn_blocks, 256>>>(ijw1, ijw2, lw1, nbr, tar, E);
    table_kernel<<<8, 256>>>(cw1, cb1, cw2, cb2, cw3, cb3);
    scn_mma_kernel<<<(E + BE - 1) / BE, 256, SMEM_SZ>>>(
        x, tar, beta, ijb1, ijb2, lb1, lw2, lb2, out, E);
}